// round 5
// baseline (speedup 1.0000x reference)
#include <cuda_runtime.h>
#include <stdint.h>

// Gather: out[r, :] = table[idx[r], :]
// rows = 819200, D = 64 floats = 16 float4 per row.
// 16 threads cooperate per row; each 16-thread group handles RPT=8
// consecutive rows. All long-latency loads batched up-front:
//   - 8 indices loaded as two int4 (2 LDG.128 instead of 8 LDG.32)
//   - 8 independent table float4 loads in flight (MLP=8)
//   - 8 streaming stores

#define D_VEC 16            // float4s per row (64 floats)
#define THREADS 256
#define RPT 8               // rows per 16-thread group iteration

__global__ __launch_bounds__(THREADS)
void gather_kernel(const int* __restrict__ indices,
                   const float4* __restrict__ table,
                   float4* __restrict__ out,
                   int num_rows)
{
    int t = blockIdx.x * blockDim.x + threadIdx.x;
    int lane = t & 15;                 // which float4 within a row
    int rowBase = (t >> 4) * RPT;      // first of RPT consecutive rows

    if (rowBase >= num_rows) return;

    if (rowBase + RPT <= num_rows) {
        // 1) vectorized index loads: 8 ints = 2x int4 (rowBase % 8 == 0,
        //    so 32B-aligned given a 16B+ aligned base allocation)
        const int4* ip = (const int4*)(indices + rowBase);
        int4 i0 = __ldg(&ip[0]);
        int4 i1 = __ldg(&ip[1]);
        int idx[RPT] = { i0.x, i0.y, i0.z, i0.w, i1.x, i1.y, i1.z, i1.w };

        // 2) batch the table loads (independent -> MLP=8 per thread)
        float4 v[RPT];
#pragma unroll
        for (int u = 0; u < RPT; u++)
            v[u] = __ldg(&table[(size_t)idx[u] * D_VEC + lane]);

        // 3) streaming stores (write-once output; don't pollute L2)
#pragma unroll
        for (int u = 0; u < RPT; u++)
            __stcs(&out[(size_t)(rowBase + u) * D_VEC + lane], v[u]);
    } else {
        // tail (unaligned-safe scalar path)
        for (int u = 0; u < RPT; u++) {
            int r = rowBase + u;
            if (r >= num_rows) break;
            int idx = __ldg(&indices[r]);
            float4 v = __ldg(&table[(size_t)idx * D_VEC + lane]);
            __stcs(&out[(size_t)r * D_VEC + lane], v);
        }
    }
}

extern "C" void kernel_launch(void* const* d_in, const int* in_sizes, int n_in,
                              void* d_out, int out_size)
{
    const int* indices = (const int*)d_in[0];       // [B*F] int32
    const float4* table = (const float4*)d_in[1];   // [V, 64] f32 as float4
    float4* out = (float4*)d_out;

    int num_rows = in_sizes[0];                     // 819200
    long long groups = ((long long)num_rows + RPT - 1) / RPT;   // 16-thread groups
    long long total_threads = groups * 16;
    int blocks = (int)((total_threads + THREADS - 1) / THREADS);

    gather_kernel<<<blocks, THREADS>>>(indices, table, out, num_rows);
}

// round 6
// speedup vs baseline: 1.0253x; 1.0253x over previous
#include <cuda_runtime.h>
#include <stdint.h>

// Gather: out[r, :] = table[idx[r], :]
// rows = 819200, D = 64 floats = 16 float4 per row.
// 16 threads per row; each 16-thread group handles RPT=8 consecutive rows.
// Table loads use __ldcg (L2-only): the 143MB distinct working set never
// hits L1, so skip L1 allocation/replay overhead entirely.
// Output uses __stcs streaming stores so the write stream doesn't evict
// the duplicate-capturing table lines from L2.

#define D_VEC 16            // float4s per row (64 floats)
#define THREADS 256
#define RPT 8               // rows per 16-thread group iteration

__global__ __launch_bounds__(THREADS)
void gather_kernel(const int* __restrict__ indices,
                   const float4* __restrict__ table,
                   float4* __restrict__ out,
                   int num_rows)
{
    int t = blockIdx.x * blockDim.x + threadIdx.x;
    int lane = t & 15;                 // which float4 within a row
    int rowBase = (t >> 4) * RPT;      // first of RPT consecutive rows

    if (rowBase >= num_rows) return;

    if (rowBase + RPT <= num_rows) {
        // 1) vectorized index loads: 8 ints = 2x int4 broadcast (L1-cached)
        const int4* ip = (const int4*)(indices + rowBase);
        int4 i0 = __ldg(&ip[0]);
        int4 i1 = __ldg(&ip[1]);
        int idx[RPT] = { i0.x, i0.y, i0.z, i0.w, i1.x, i1.y, i1.z, i1.w };

        // 2) batch table loads, L2-only (bypass useless L1 allocation)
        float4 v[RPT];
#pragma unroll
        for (int u = 0; u < RPT; u++)
            v[u] = __ldcg(&table[(size_t)idx[u] * D_VEC + lane]);

        // 3) streaming stores (write-once output; evict-first in L2)
#pragma unroll
        for (int u = 0; u < RPT; u++)
            __stcs(&out[(size_t)(rowBase + u) * D_VEC + lane], v[u]);
    } else {
        // tail (scalar-safe path)
        for (int u = 0; u < RPT; u++) {
            int r = rowBase + u;
            if (r >= num_rows) break;
            int idx = __ldg(&indices[r]);
            float4 v = __ldcg(&table[(size_t)idx * D_VEC + lane]);
            __stcs(&out[(size_t)r * D_VEC + lane], v);
        }
    }
}

extern "C" void kernel_launch(void* const* d_in, const int* in_sizes, int n_in,
                              void* d_out, int out_size)
{
    const int* indices = (const int*)d_in[0];       // [B*F] int32
    const float4* table = (const float4*)d_in[1];   // [V, 64] f32 as float4
    float4* out = (float4*)d_out;

    int num_rows = in_sizes[0];                     // 819200
    long long groups = ((long long)num_rows + RPT - 1) / RPT;   // 16-thread groups
    long long total_threads = groups * 16;
    int blocks = (int)((total_threads + THREADS - 1) / THREADS);

    gather_kernel<<<blocks, THREADS>>>(indices, table, out, num_rows);
}